// round 13
// baseline (speedup 1.0000x reference)
#include <cuda_runtime.h>
#include <cuda_fp16.h>
#include <cuda_bf16.h>

#define WAY   5
#define NQ    75
#define CIN   640
#define NTOK  512
#define CP    64
#define PAIRS (WAY*NQ)          /* 375 */
#define BN_EPS 1e-5f
#define GN_EPS 1e-5f
#define L2_EPS 1e-8f
#define LOG2E  1.4426950408889634f

/* scratch (device globals)
 * g_S/g_Q: [batch][tok 512][ch 64], channels PERMUTED by perm8() */
__device__ float g_S[WAY*NTOK*CP];
__device__ float g_Q[NQ*NTOK*CP];
__device__ float g_mS[WAY*NTOK];
__device__ float g_mQ[NQ*NTOK];
__device__ float g_G[(WAY+NQ)*CP*CP];
__device__ float g_bar[(WAY+NQ)*CP];
__device__ float g_as[PAIRS*NTOK];
__device__ float g_aq[PAIRS*NTOK];
__device__ float g_ps[PAIRS*CIN];
__device__ float g_pq[PAIRS*CIN];
__device__ float g_wsum[CP];
__device__ float g_scale[CP];
__device__ float g_bias[CP];

__device__ __forceinline__ float ex2(float x) {
    float y;
    asm("ex2.approx.ftz.f32 %0, %1;" : "=f"(y) : "f"(x));
    return y;
}
__device__ __forceinline__ float warp_sum(float v) {
    #pragma unroll
    for (int o = 16; o; o >>= 1) v += __shfl_xor_sync(0xffffffffu, v, o);
    return v;
}
__device__ __forceinline__ unsigned to_tf32(float f) {
    unsigned u;
    asm("cvt.rna.tf32.f32 %0, %1;" : "=r"(u) : "f"(f));
    return u;
}
__device__ __forceinline__ int perm8(int c) {
    return (c & ~7) | ((c & 3) * 2) | ((c >> 2) & 1);
}
__device__ __forceinline__ void mma_tf32(float* d, unsigned a0, unsigned a1,
                                         unsigned a2, unsigned a3,
                                         unsigned b0, unsigned b1) {
    asm volatile(
        "mma.sync.aligned.m16n8k8.row.col.f32.tf32.tf32.f32 "
        "{%0,%1,%2,%3}, {%4,%5,%6,%7}, {%8,%9}, {%0,%1,%2,%3};"
        : "+f"(d[0]), "+f"(d[1]), "+f"(d[2]), "+f"(d[3])
        : "r"(a0), "r"(a1), "r"(a2), "r"(a3), "r"(b0), "r"(b1));
}

/* ------------- K-pre: BN fold + weight row sums ------------- */
__global__ void kpre(const float* __restrict__ W, const float* __restrict__ gamma,
                     const float* __restrict__ beta, const float* __restrict__ mean,
                     const float* __restrict__ var) {
    int t = threadIdx.x;
    int o = t >> 2, ln = t & 3;
    float s = 0.f;
    for (int c = ln; c < CIN; c += 4) s += W[o*CIN + c];
    s += __shfl_xor_sync(0xffffffffu, s, 1);
    s += __shfl_xor_sync(0xffffffffu, s, 2);
    if (ln == 0) {
        g_wsum[o] = s;
        float sc = gamma[o] * rsqrtf(var[o] + BN_EPS);
        g_scale[o] = sc;
        g_bias[o]  = beta[o] - mean[o] * sc;
    }
}

/* ------------- K0 (tf32 mma): projection -> transposed+permuted [tok][64] ------------- */
#define PJ_SMEM (64*68*4 + 128*68*4 + (64*3 + 128 + 128*2 + 128)*4)   /* 55040 B */

__global__ void __launch_bounds__(256, 2) kproj(const float* __restrict__ sup,
                                                const float* __restrict__ qry,
                                                const float* __restrict__ W) {
    extern __shared__ unsigned pj_sm[];
    unsigned* Wm = pj_sm;                    // [64][68] tf32
    unsigned* Xm = Wm + 64*68;               // [128][68] tf32 (x transposed)
    float* wsum_s  = (float*)(Xm + 128*68);  // [64]
    float* scale_s = wsum_s + 64;
    float* bias_s  = scale_s + 64;
    float* minv    = bias_s + 64;            // [128]
    float* ssqred  = minv + 128;             // [128][2]
    float* linv    = ssqred + 256;           // [128]

    int b  = blockIdx.x >> 2;
    int t0 = (blockIdx.x & 3) * 128;
    const float* x  = (b < WAY) ? sup + (size_t)b*CIN*NTOK : qry + (size_t)(b-WAY)*CIN*NTOK;
    float* outp     = (b < WAY) ? g_S + b*NTOK*CP          : g_Q + (b-WAY)*NTOK*CP;
    float* moutp    = (b < WAY) ? g_mS + b*NTOK            : g_mQ + (b-WAY)*NTOK;

    int t = threadIdx.x, lane = t & 31, warp = t >> 5;
    int wi = warp >> 2, wj = warp & 3;
    int la = lane >> 2, lb = lane & 3;

    if (t < 64) {
        wsum_s[t]  = g_wsum[t];
        scale_s[t] = g_scale[t];
        bias_s[t]  = g_bias[t];
    }

    float acc[2][4][4];
    #pragma unroll
    for (int m = 0; m < 2; m++)
        #pragma unroll
        for (int n = 0; n < 4; n++)
            #pragma unroll
            for (int e = 0; e < 4; e++) acc[m][n][e] = 0.f;
    float cs = 0.f;

    for (int ch = 0; ch < 10; ch++) {
        __syncthreads();
        #pragma unroll
        for (int j = 0; j < 4; j++) {
            int idx = t + j*256;
            int o = idx >> 4, c4 = (idx & 15) << 2;
            float4 v = *(const float4*)(W + (size_t)o*CIN + ch*64 + c4);
            *(uint4*)(Wm + o*68 + c4) =
                make_uint4(to_tf32(v.x), to_tf32(v.y), to_tf32(v.z), to_tf32(v.w));
        }
        #pragma unroll
        for (int it = 0; it < 8; it++) {
            int fidx = t + it*256;
            int c = fidx >> 5, f4 = (fidx & 31) << 2;
            float4 v = *(const float4*)(x + (size_t)(ch*64 + c)*NTOK + t0 + f4);
            Xm[(f4+0)*68 + c] = to_tf32(v.x);
            Xm[(f4+1)*68 + c] = to_tf32(v.y);
            Xm[(f4+2)*68 + c] = to_tf32(v.z);
            Xm[(f4+3)*68 + c] = to_tf32(v.w);
        }
        __syncthreads();
        if (t < 128) {
            #pragma unroll 8
            for (int c = 0; c < 64; c++) {
                int cc = (c + t) & 63;
                cs += __uint_as_float(Xm[t*68 + cc]);
            }
        }
        #pragma unroll
        for (int ks = 0; ks < 8; ks++) {
            int k0 = ks*8 + 2*lb;
            uint2 af[2][2];
            #pragma unroll
            for (int m = 0; m < 2; m++) {
                int r0 = wi*32 + m*16 + la;
                af[m][0] = *(uint2*)(Wm + r0*68 + k0);
                af[m][1] = *(uint2*)(Wm + (r0+8)*68 + k0);
            }
            uint2 bf[4];
            #pragma unroll
            for (int n = 0; n < 4; n++) {
                int j0 = wj*32 + n*8 + la;
                bf[n] = *(uint2*)(Xm + j0*68 + k0);
            }
            #pragma unroll
            for (int m = 0; m < 2; m++)
                #pragma unroll
                for (int n = 0; n < 4; n++)
                    mma_tf32(acc[m][n], af[m][0].x, af[m][1].x,
                             af[m][0].y, af[m][1].y, bf[n].x, bf[n].y);
        }
    }
    __syncthreads();
    if (t < 128) minv[t] = cs * (1.f/CIN);
    __syncthreads();

    #pragma unroll
    for (int n = 0; n < 4; n++)
        #pragma unroll
        for (int p = 0; p < 2; p++) {
            int col = wj*32 + n*8 + 2*lb + p;
            float mv = minv[col];
            float s4 = 0.f;
            #pragma unroll
            for (int m = 0; m < 2; m++)
                #pragma unroll
                for (int h = 0; h < 2; h++) {
                    int r = wi*32 + m*16 + la + 8*h;
                    float y = acc[m][n][2*h+p] - wsum_s[r]*mv;
                    y = fmaxf(fmaf(y, scale_s[r], bias_s[r]), 0.f);
                    acc[m][n][2*h+p] = y;
                    s4 = fmaf(y, y, s4);
                }
            s4 += __shfl_xor_sync(0xffffffffu, s4, 4);
            s4 += __shfl_xor_sync(0xffffffffu, s4, 8);
            s4 += __shfl_xor_sync(0xffffffffu, s4, 16);
            if (la == 0) ssqred[col*2 + wi] = s4;
        }
    __syncthreads();
    if (t < 128) {
        linv[t] = 1.f / fmaxf(sqrtf(ssqred[t*2] + ssqred[t*2+1]), L2_EPS);
        moutp[t0 + t] = minv[t];
    }
    __syncthreads();

    float* sout = (float*)pj_sm;             // [128][68]
    #pragma unroll
    for (int n = 0; n < 4; n++)
        #pragma unroll
        for (int p = 0; p < 2; p++) {
            int col = wj*32 + n*8 + 2*lb + p;
            float lv = linv[col];
            #pragma unroll
            for (int m = 0; m < 2; m++)
                #pragma unroll
                for (int h = 0; h < 2; h++) {
                    int r = wi*32 + m*16 + la + 8*h;
                    sout[col*68 + perm8(r)] = acc[m][n][2*h+p] * lv;
                }
        }
    __syncthreads();
    #pragma unroll
    for (int j = 0; j < 8; j++) {
        int idx = t + j*256;
        int col = idx >> 4, c4 = (idx & 15) << 2;
        *(float4*)(outp + (size_t)(t0 + col)*CP + c4) = *(float4*)&sout[col*68 + c4];
    }
}

/* ------------- Kgram: per batch token-mean + centered Gram (64x64) ------------- */
__global__ __launch_bounds__(256) void kgram() {
    __shared__ float Xs[128*68];
    __shared__ float abar_s[64];

    int b = blockIdx.x;
    const float* X = (b < WAY) ? g_S + (size_t)b*NTOK*CP
                               : g_Q + (size_t)(b-WAY)*NTOK*CP;
    int t = threadIdx.x;

    float csum = 0.f;
    for (int ck = 0; ck < 4; ck++) {
        for (int idx = t; idx < 128*16; idx += 256) {
            int r = idx >> 4, c4 = (idx & 15) << 2;
            *(float4*)&Xs[r*68 + c4] = *(const float4*)(X + (size_t)(ck*128 + r)*CP + c4);
        }
        __syncthreads();
        if (t < 64) {
            #pragma unroll 8
            for (int r = 0; r < 128; r++) csum += Xs[r*68 + t];
        }
        __syncthreads();
    }
    if (t < 64) {
        float m = csum * (1.f/512.f);
        abar_s[t] = m;
        g_bar[b*CP + t] = m;
    }
    __syncthreads();

    float gacc[4][4];
    #pragma unroll
    for (int i = 0; i < 4; i++)
        #pragma unroll
        for (int j = 0; j < 4; j++) gacc[i][j] = 0.f;
    int a0 = (t >> 4) * 4, b0 = (t & 15) * 4;

    for (int ck = 0; ck < 4; ck++) {
        for (int idx = t; idx < 128*16; idx += 256) {
            int r = idx >> 4, c4 = (idx & 15) << 2;
            float4 v = *(const float4*)(X + (size_t)(ck*128 + r)*CP + c4);
            v.x -= abar_s[c4+0]; v.y -= abar_s[c4+1];
            v.z -= abar_s[c4+2]; v.w -= abar_s[c4+3];
            *(float4*)&Xs[r*68 + c4] = v;
        }
        __syncthreads();
        #pragma unroll 4
        for (int r = 0; r < 128; r++) {
            float4 av = *(float4*)&Xs[r*68 + a0];
            float4 bv = *(float4*)&Xs[r*68 + b0];
            float aa[4] = {av.x, av.y, av.z, av.w};
            float bb[4] = {bv.x, bv.y, bv.z, bv.w};
            #pragma unroll
            for (int i = 0; i < 4; i++)
                #pragma unroll
                for (int j = 0; j < 4; j++)
                    gacc[i][j] = fmaf(aa[i], bb[j], gacc[i][j]);
        }
        __syncthreads();
    }
    #pragma unroll
    for (int i = 0; i < 4; i++)
        #pragma unroll
        for (int j = 0; j < 4; j++)
            g_G[(size_t)b*CP*CP + (a0+i)*CP + b0+j] = gacc[i][j];
}

/* ------------- Kpass: r8 structure, 512 threads (16 warps) for issue-bound relief ------
 * CTA tile per stripe: 128 B-cols x 512 A-rows (4 ab blocks of 128).
 * Main GEMM warp tile 32x32 (wi 0-3 rows, wj 0-3 cols). Stats warp tile 32x16.
 * Attn phase: 1 A-row per thread.
 */
#define KP_SMEM_BYTES 231168

extern "C" __global__ void __launch_bounds__(512, 1) kpass() {
    extern __shared__ unsigned char kp_sm[];
    unsigned* Bstf = (unsigned*)kp_sm;            // [128][68] tf32
    unsigned* Astf = Bstf + 128*68;               // [128][68]
    unsigned* Gm   = Astf + 128*68;               // [64][68]
    __half*  Ebuf  = (__half*)(Gm + 64*68);       // [512][136]
    float* zred    = (float*)(Ebuf + 512*136);    // [128][5]
    float* bscale  = zred + 128*5;                // [128]
    float* bofs    = bscale + 128;
    float* bmean   = bofs + 128;
    float* zsum    = bmean + 128;
    float* abar    = zsum + 128;                  // [64]

    int bid = blockIdx.x;
    int mode = (bid >= PAIRS);
    int pair = bid - mode*PAIRS;
    int qq = pair / WAY, ww = pair % WAY;
    const float *A, *B, *Gp, *barp;
    float* outp;
    if (mode == 0) {
        A = g_S + (size_t)ww*NTOK*CP;  B = g_Q + (size_t)qq*NTOK*CP;
        Gp = g_G + (size_t)ww*CP*CP;   barp = g_bar + ww*CP;
        outp = g_as + pair*NTOK;
    } else {
        A = g_Q + (size_t)qq*NTOK*CP;  B = g_S + (size_t)ww*NTOK*CP;
        Gp = g_G + (size_t)(WAY+qq)*CP*CP;  barp = g_bar + (WAY+qq)*CP;
        outp = g_aq + pair*NTOK;
    }

    int t = threadIdx.x, lane = t & 31, warp = t >> 5;   /* 16 warps */
    int wi = warp >> 2, wj = warp & 3;                   /* 4x4 */
    int la = lane >> 2, lb = lane & 3;

    for (int i = t; i < 64*64; i += 512)
        Gm[(i >> 6)*68 + (i & 63)] = to_tf32(Gp[i]);
    if (t < 64) abar[t] = barp[t];

    float attn = 0.f;     /* this thread's A-row (row = t) */

    for (int sb = 0; sb < 4; sb++) {
        __syncthreads();
        /* stage B stripe */
        #pragma unroll
        for (int j = 0; j < 4; j++) {
            int idx = t + j*512;
            int r = idx >> 4, c4 = (idx & 15) << 2;
            float4 v = *(const float4*)(B + (size_t)(sb*128 + r)*CP + c4);
            *(uint4*)(Bstf + r*68 + c4) =
                make_uint4(to_tf32(v.x), to_tf32(v.y), to_tf32(v.z), to_tf32(v.w));
        }
        if (t < 128) zsum[t] = 0.f;
        __syncthreads();

        /* stats: H = Bstf*G' (128x64), warp tile 32 rows x 16 cols */
        {
            float sacc[2][2][4];
            #pragma unroll
            for (int m = 0; m < 2; m++)
                #pragma unroll
                for (int n = 0; n < 2; n++)
                    #pragma unroll
                    for (int e = 0; e < 4; e++) sacc[m][n][e] = 0.f;
            #pragma unroll
            for (int ks = 0; ks < 8; ks++) {
                int k0 = ks*8 + 2*lb;
                uint2 saf[2][2];
                #pragma unroll
                for (int m = 0; m < 2; m++) {
                    int r0 = wi*32 + m*16 + la;
                    saf[m][0] = *(uint2*)(Bstf + r0*68 + k0);
                    saf[m][1] = *(uint2*)(Bstf + (r0+8)*68 + k0);
                }
                uint2 sbf[2];
                #pragma unroll
                for (int n = 0; n < 2; n++) {
                    int j0 = wj*16 + n*8 + la;
                    sbf[n] = *(uint2*)(Gm + j0*68 + k0);
                }
                #pragma unroll
                for (int m = 0; m < 2; m++)
                    #pragma unroll
                    for (int n = 0; n < 2; n++)
                        mma_tf32(sacc[m][n], saf[m][0].x, saf[m][1].x,
                                 saf[m][0].y, saf[m][1].y, sbf[n].x, sbf[n].y);
            }
            #pragma unroll
            for (int m = 0; m < 2; m++)
                #pragma unroll
                for (int h = 0; h < 2; h++) {
                    int j = wi*32 + m*16 + la + 8*h;
                    float s = 0.f;
                    #pragma unroll
                    for (int n = 0; n < 2; n++)
                        #pragma unroll
                        for (int p = 0; p < 2; p++) {
                            int ch = wj*16 + n*8 + 2*lb + p;
                            s = fmaf(sacc[m][n][2*h+p],
                                     __uint_as_float(Bstf[j*68 + ch]), s);
                        }
                    s += __shfl_xor_sync(0xffffffffu, s, 1);
                    s += __shfl_xor_sync(0xffffffffu, s, 2);
                    if (lb == 0) zred[j*5 + wj] = s;
                }
        }
        if (t < 128) {
            float m = 0.f;
            #pragma unroll 8
            for (int c = 0; c < 64; c++)
                m = fmaf(__uint_as_float(Bstf[t*68 + c]), abar[c], m);
            bmean[t] = m;
        }
        __syncthreads();
        if (t < 128) {
            float var = (zred[t*5] + zred[t*5+1] + zred[t*5+2] + zred[t*5+3]) * (1.f/511.f);
            float sc = LOG2E / (5.f * sqrtf(var + GN_EPS));
            bscale[t] = sc;
            bofs[t] = bmean[t] * sc;
        }
        __syncthreads();

        float cs[8], co[8];
        #pragma unroll
        for (int n = 0; n < 4; n++)
            #pragma unroll
            for (int p = 0; p < 2; p++) {
                int col = wj*32 + n*8 + 2*lb + p;
                cs[2*n+p] = bscale[col];
                co[2*n+p] = bofs[col];
            }

        for (int ab = 0; ab < 4; ab++) {
            __syncthreads();
            #pragma unroll
            for (int j = 0; j < 4; j++) {
                int idx = t + j*512;
                int r = idx >> 4, c4 = (idx & 15) << 2;
                float4 v = *(const float4*)(A + (size_t)(ab*128 + r)*CP + c4);
                *(uint4*)(Astf + r*68 + c4) =
                    make_uint4(to_tf32(v.x), to_tf32(v.y), to_tf32(v.z), to_tf32(v.w));
            }
            __syncthreads();

            float acc[2][4][4];
            #pragma unroll
            for (int m = 0; m < 2; m++)
                #pragma unroll
                for (int n = 0; n < 4; n++)
                    #pragma unroll
                    for (int e = 0; e < 4; e++) acc[m][n][e] = 0.f;

            #pragma unroll
            for (int ks = 0; ks < 8; ks++) {
                int k0 = ks*8 + 2*lb;
                uint2 af[2][2];
                #pragma unroll
                for (int m = 0; m < 2; m++) {
                    int r0 = wi*32 + m*16 + la;
                    af[m][0] = *(uint2*)(Astf + r0*68 + k0);
                    af[m][1] = *(uint2*)(Astf + (r0+8)*68 + k0);
                }
                uint2 bf[4];
                #pragma unroll
                for (int n = 0; n < 4; n++) {
                    int j0 = wj*32 + n*8 + la;
                    bf[n] = *(uint2*)(Bstf + j0*68 + k0);
                }
                #pragma unroll
                for (int m = 0; m < 2; m++)
                    #pragma unroll
                    for (int n = 0; n < 4; n++)
                        mma_tf32(acc[m][n], af[m][0].x, af[m][1].x,
                                 af[m][0].y, af[m][1].y, bf[n].x, bf[n].y);
            }

            /* exp -> Ebuf, Z partials */
            float zp[8];
            #pragma unroll
            for (int i = 0; i < 8; i++) zp[i] = 0.f;
            #pragma unroll
            for (int m = 0; m < 2; m++)
                #pragma unroll
                for (int h = 0; h < 2; h++) {
                    int arow = ab*128 + wi*32 + m*16 + la + 8*h;
                    __half* erow = Ebuf + arow*136 + wj*32;
                    #pragma unroll
                    for (int n = 0; n < 4; n++) {
                        float e0 = ex2(fmaf(acc[m][n][2*h+0], cs[2*n+0], -co[2*n+0]));
                        float e1 = ex2(fmaf(acc[m][n][2*h+1], cs[2*n+1], -co[2*n+1]));
                        zp[2*n+0] += e0;
                        zp[2*n+1] += e1;
                        *(__half2*)(erow + n*8 + 2*lb) = __floats2half2_rn(e0, e1);
                    }
                }
            #pragma unroll
            for (int n = 0; n < 4; n++)
                #pragma unroll
                for (int p = 0; p < 2; p++) {
                    float v = zp[2*n+p];
                    v += __shfl_xor_sync(0xffffffffu, v, 4);
                    v += __shfl_xor_sync(0xffffffffu, v, 8);
                    v += __shfl_xor_sync(0xffffffffu, v, 16);
                    if (la == 0)
                        zred[(wj*32 + n*8 + 2*lb + p)*5 + wi] = v;
                }
            __syncthreads();
            if (t < 128)
                zsum[t] += zred[t*5] + zred[t*5+1] + zred[t*5+2] + zred[t*5+3];
        }
        __syncthreads();
        if (t < 128) zsum[t] = 1.f / zsum[t];
        __syncthreads();

        /* attn accumulation: one A-row per thread */
        {
            const __half* rp = Ebuf + t*136;
            #pragma unroll 4
            for (int jj = 0; jj < 16; jj++) {
                uint4 e = *(const uint4*)(rp + jj*8);
                const __half2* h = (const __half2*)&e;
                #pragma unroll
                for (int u = 0; u < 4; u++) {
                    float2 f = __half22float2(h[u]);
                    int c = jj*8 + u*2;
                    attn = fmaf(f.x, zsum[c], fmaf(f.y, zsum[c+1], attn));
                }
            }
        }
    }
    outp[t] = attn;
}

/* ------------- KpoolS: pooled_s raw = attn_s x sup[w] ------------- */
#define PS_SMEM ((64*129 + 75*128) * 4)   /* 71424 B */

__global__ __launch_bounds__(256) void kpoolS(const float* __restrict__ sup) {
    extern __shared__ float ps_sm[];
    float* xs  = ps_sm;              // [64][129]
    float* asb = ps_sm + 64*129;     // [75][128]

    int w = blockIdx.x / 10, ct = blockIdx.x % 10;
    int c0 = ct*64;
    int t = threadIdx.x;
    int c = t & 63, qb = t >> 6;
    const float* X = sup + (size_t)w*CIN*NTOK + (size_t)c0*NTOK;

    float acc[19];
    #pragma unroll
    for (int j = 0; j < 19; j++) acc[j] = 0.f;

    for (int i0 = 0; i0 < NTOK; i0 += 128) {
        __syncthreads();
        for (int idx = t; idx < 64*32; idx += 256) {
            int r = idx >> 5, i4 = (idx & 31) << 2;
            float4 v = *(const float4*)(X + (size_t)r*NTOK + i0 + i4);
            xs[r*129 + i4+0] = v.x; xs[r*129 + i4+1] = v.y;
            xs[r*129 + i4+2] = v.z; xs[r*129 + i4+3] = v.w;
        }
        for (int idx = t; idx < 75*32; idx += 256) {
            int r = idx / 32, i4 = (idx & 31) << 2;
            *(float4*)&asb[r*128 + i4] =
                *(const float4*)(g_as + (size_t)(r*WAY + w)*NTOK + i0 + i4);
        }
        __syncthreads();
        for (int i = 0; i < 128; i += 4) {
            float x0 = xs[c*129 + i],   x1 = xs[c*129 + i+1];
            float x2 = xs[c*129 + i+2], x3 = xs[c*129 + i+3];
            #pragma unroll
            for (int j = 0; j < 19; j++) {
                int q = qb + 4*j;
                if (q < NQ) {
                    float4 a = *(float4*)&asb[q*128 + i];
                    acc[j] = fmaf(a.x, x0, fmaf(a.y, x1, fmaf(a.z, x2, fmaf(a.w, x3, acc[j]))));
                }
            }
        }
    }
    #pragma unroll
    for (int j = 0; j < 19; j++) {
        int q = qb + 4*j;
        if (q < NQ) g_ps[(size_t)(q*WAY + w)*CIN + c0 + c] = acc[j];
    }
}

/* ------------- KpoolQ: pooled_q raw = attn_q x qry[q] ------------- */
__global__ __launch_bounds__(256) void kpoolQ(const float* __restrict__ qry) {
    __shared__ float xs[64*129];
    __shared__ float aqb[5*128];
    __shared__ float red[5*64*4];

    int q = blockIdx.x / 10, ct = blockIdx.x % 10;
    int c0 = ct*64;
    int t = threadIdx.x;
    int c = t & 63, g = t >> 6;
    const float* X = qry + (size_t)q*CIN*NTOK + (size_t)c0*NTOK;

    float acc[5] = {0.f, 0.f, 0.f, 0.f, 0.f};

    for (int i0 = 0; i0 < NTOK; i0 += 128) {
        __syncthreads();
        for (int idx = t; idx < 64*32; idx += 256) {
            int r = idx >> 5, i4 = (idx & 31) << 2;
            float4 v = *(const float4*)(X + (size_t)r*NTOK + i0 + i4);
            xs[r*129 + i4+0] = v.x; xs[r*129 + i4+1] = v.y;
            xs[r*129 + i4+2] = v.z; xs[r*129 + i4+3] = v.w;
        }
        for (int idx = t; idx < 5*32; idx += 256) {
            int r = idx / 32, i4 = (idx & 31) << 2;
            *(float4*)&aqb[r*128 + i4] =
                *(const float4*)(g_aq + (size_t)(q*WAY + r)*NTOK + i0 + i4);
        }
        __syncthreads();
        for (int i = g*32; i < g*32 + 32; i += 4) {
            float x0 = xs[c*129 + i],   x1 = xs[c*129 + i+1];
            float x2 = xs[c*129 + i+2], x3 = xs[c*129 + i+3];
            #pragma unroll
            for (int wv = 0; wv < 5; wv++) {
                float4 a = *(float4*)&aqb[wv*128 + i];
                acc[wv] = fmaf(a.x, x0, fmaf(a.y, x1, fmaf(a.z, x2, fmaf(a.w, x3, acc[wv]))));
            }
        }
    }
    #pragma unroll
    for (int wv = 0; wv < 5; wv++) red[(wv*64 + c)*4 + g] = acc[wv];
    __syncthreads();
    for (int idx = t; idx < 5*64; idx += 256) {
        int wv = idx >> 6, cc = idx & 63;
        float s = red[idx*4] + red[idx*4+1] + red[idx*4+2] + red[idx*4+3];
        g_pq[(size_t)(q*WAY + wv)*CIN + c0 + cc] = s;
    }
}

/* ------------- Kcos: mean corrections + cosine sim ------------- */
__global__ __launch_bounds__(128) void kcos(float* __restrict__ out) {
    __shared__ float rbuf[4*5];
    int pair = blockIdx.x, q = pair / WAY, w = pair % WAY;
    int t = threadIdx.x, lane = t & 31, wp = t >> 5;

    float cS = 0.f, cQ = 0.f;
    for (int i = t; i < NTOK; i += 128) {
        cS = fmaf(g_as[pair*NTOK + i], g_mS[w*NTOK + i], cS);
        cQ = fmaf(g_aq[pair*NTOK + i], g_mQ[q*NTOK + i], cQ);
    }
    cS = warp_sum(cS); cQ = warp_sum(cQ);
    if (lane == 0) { rbuf[wp*5+0] = cS; rbuf[wp*5+1] = cQ; }
    __syncthreads();
    cS = rbuf[0] + rbuf[5] + rbuf[10] + rbuf[15];
    cQ = rbuf[1] + rbuf[6] + rbuf[11] + rbuf[16];
    __syncthreads();

    float dp = 0.f, ns = 0.f, nq2 = 0.f;
    for (int c = t; c < CIN; c += 128) {
        float a = g_ps[(size_t)pair*CIN + c] - cS;
        float b = g_pq[(size_t)pair*CIN + c] - cQ;
        dp = fmaf(a, b, dp); ns = fmaf(a, a, ns); nq2 = fmaf(b, b, nq2);
    }
    dp = warp_sum(dp); ns = warp_sum(ns); nq2 = warp_sum(nq2);
    if (lane == 0) { rbuf[wp*5+0] = dp; rbuf[wp*5+1] = ns; rbuf[wp*5+2] = nq2; }
    __syncthreads();
    if (t == 0) {
        dp  = rbuf[0] + rbuf[5] + rbuf[10] + rbuf[15];
        ns  = rbuf[1] + rbuf[6] + rbuf[11] + rbuf[16];
        nq2 = rbuf[2] + rbuf[7] + rbuf[12] + rbuf[17];
        float psn = fmaxf(sqrtf(ns)  * (1.f/512.f), L2_EPS);
        float pqn = fmaxf(sqrtf(nq2) * (1.f/512.f), L2_EPS);
        out[pair] = (dp * (1.f/(512.f*512.f))) / (psn * pqn) * 5.f;
    }
}

/* ------------- launcher ------------- */
extern "C" void kernel_launch(void* const* d_in, const int* in_sizes, int n_in,
                              void* d_out, int out_size) {
    const float* sup   = (const float*)d_in[0];
    const float* qry   = (const float*)d_in[1];
    const float* W     = (const float*)d_in[2];
    const float* gamma = (const float*)d_in[3];
    const float* beta  = (const float*)d_in[4];
    const float* mean  = (const float*)d_in[5];
    const float* var   = (const float*)d_in[6];
    float* out = (float*)d_out;

    cudaFuncSetAttribute(kpass, cudaFuncAttributeMaxDynamicSharedMemorySize, KP_SMEM_BYTES);
    cudaFuncSetAttribute(kproj, cudaFuncAttributeMaxDynamicSharedMemorySize, PJ_SMEM);
    cudaFuncSetAttribute(kpoolS, cudaFuncAttributeMaxDynamicSharedMemorySize, PS_SMEM);

    kpre<<<1, 256>>>(W, gamma, beta, mean, var);
    kproj<<<(WAY+NQ)*4, 256, PJ_SMEM>>>(sup, qry, W);
    kgram<<<WAY+NQ, 256>>>();
    kpass<<<2*PAIRS, 512, KP_SMEM_BYTES>>>();
    kpoolS<<<WAY*10, 256, PS_SMEM>>>(sup);
    kpoolQ<<<NQ*10, 256>>>(qry);
    kcos<<<PAIRS, 128>>>(out);
}

// round 15
// speedup vs baseline: 1.0979x; 1.0979x over previous
#include <cuda_runtime.h>
#include <cuda_fp16.h>
#include <cuda_bf16.h>

#define WAY   5
#define NQ    75
#define CIN   640
#define NTOK  512
#define CP    64
#define PAIRS (WAY*NQ)          /* 375 */
#define BN_EPS 1e-5f
#define GN_EPS 1e-5f
#define L2_EPS 1e-8f
#define LOG2E  1.4426950408889634f

/* scratch (device globals)
 * g_S/g_Q: [batch][tok 512][ch 64], channels PERMUTED by perm8() */
__device__ float g_S[WAY*NTOK*CP];
__device__ float g_Q[NQ*NTOK*CP];
__device__ float g_mS[WAY*NTOK];
__device__ float g_mQ[NQ*NTOK];
__device__ float g_G[(WAY+NQ)*CP*CP];
__device__ float g_bar[(WAY+NQ)*CP];
__device__ float g_as[PAIRS*NTOK];
__device__ float g_aq[PAIRS*NTOK];
__device__ float g_ps[PAIRS*CIN];
__device__ float g_pq[PAIRS*CIN];

__device__ __forceinline__ float ex2(float x) {
    float y;
    asm("ex2.approx.ftz.f32 %0, %1;" : "=f"(y) : "f"(x));
    return y;
}
__device__ __forceinline__ float warp_sum(float v) {
    #pragma unroll
    for (int o = 16; o; o >>= 1) v += __shfl_xor_sync(0xffffffffu, v, o);
    return v;
}
__device__ __forceinline__ unsigned to_tf32(float f) {
    unsigned u;
    asm("cvt.rna.tf32.f32 %0, %1;" : "=r"(u) : "f"(f));
    return u;
}
__device__ __forceinline__ int perm8(int c) {
    return (c & ~7) | ((c & 3) * 2) | ((c >> 2) & 1);
}
__device__ __forceinline__ void mma_tf32(float* d, unsigned a0, unsigned a1,
                                         unsigned a2, unsigned a3,
                                         unsigned b0, unsigned b1) {
    asm volatile(
        "mma.sync.aligned.m16n8k8.row.col.f32.tf32.tf32.f32 "
        "{%0,%1,%2,%3}, {%4,%5,%6,%7}, {%8,%9}, {%0,%1,%2,%3};"
        : "+f"(d[0]), "+f"(d[1]), "+f"(d[2]), "+f"(d[3])
        : "r"(a0), "r"(a1), "r"(a2), "r"(a3), "r"(b0), "r"(b1));
}

/* ------------- K0 (tf32 mma): projection -> transposed+permuted [tok][64] -------------
 * kpre folded in: each CTA computes wsum/scale/bias itself (it reads all of W anyway).
 */
#define PJ_SMEM (64*68*4 + 128*68*4 + (64*3 + 128 + 128*2 + 128)*4)   /* 55040 B */

__global__ void __launch_bounds__(256, 2) kproj(const float* __restrict__ sup,
                                                const float* __restrict__ qry,
                                                const float* __restrict__ W,
                                                const float* __restrict__ gamma,
                                                const float* __restrict__ beta,
                                                const float* __restrict__ mean,
                                                const float* __restrict__ var) {
    extern __shared__ unsigned pj_sm[];
    unsigned* Wm = pj_sm;                    // [64][68] tf32
    unsigned* Xm = Wm + 64*68;               // [128][68] tf32 (x transposed)
    float* wsum_s  = (float*)(Xm + 128*68);  // [64]
    float* scale_s = wsum_s + 64;
    float* bias_s  = scale_s + 64;
    float* minv    = bias_s + 64;            // [128]
    float* ssqred  = minv + 128;             // [128][2]
    float* linv    = ssqred + 256;           // [128]

    int b  = blockIdx.x >> 2;
    int t0 = (blockIdx.x & 3) * 128;
    const float* x  = (b < WAY) ? sup + (size_t)b*CIN*NTOK : qry + (size_t)(b-WAY)*CIN*NTOK;
    float* outp     = (b < WAY) ? g_S + b*NTOK*CP          : g_Q + (b-WAY)*NTOK*CP;
    float* moutp    = (b < WAY) ? g_mS + b*NTOK            : g_mQ + (b-WAY)*NTOK;

    int t = threadIdx.x, lane = t & 31, warp = t >> 5;
    int wi = warp >> 2, wj = warp & 3;
    int la = lane >> 2, lb = lane & 3;

    if (t < 64) {
        float sc = gamma[t] * rsqrtf(var[t] + BN_EPS);
        scale_s[t] = sc;
        bias_s[t]  = beta[t] - mean[t] * sc;
    }

    float acc[2][4][4];
    #pragma unroll
    for (int m = 0; m < 2; m++)
        #pragma unroll
        for (int n = 0; n < 4; n++)
            #pragma unroll
            for (int e = 0; e < 4; e++) acc[m][n][e] = 0.f;
    float cs = 0.f;
    float wpart[4] = {0.f, 0.f, 0.f, 0.f};   /* W row-sum partials (row = t>>4 + 16j) */

    for (int ch = 0; ch < 10; ch++) {
        __syncthreads();
        #pragma unroll
        for (int j = 0; j < 4; j++) {
            int idx = t + j*256;
            int o = idx >> 4, c4 = (idx & 15) << 2;
            float4 v = *(const float4*)(W + (size_t)o*CIN + ch*64 + c4);
            wpart[j] += v.x + v.y + v.z + v.w;
            *(uint4*)(Wm + o*68 + c4) =
                make_uint4(to_tf32(v.x), to_tf32(v.y), to_tf32(v.z), to_tf32(v.w));
        }
        #pragma unroll
        for (int it = 0; it < 8; it++) {
            int fidx = t + it*256;
            int c = fidx >> 5, f4 = (fidx & 31) << 2;
            float4 v = *(const float4*)(x + (size_t)(ch*64 + c)*NTOK + t0 + f4);
            Xm[(f4+0)*68 + c] = to_tf32(v.x);
            Xm[(f4+1)*68 + c] = to_tf32(v.y);
            Xm[(f4+2)*68 + c] = to_tf32(v.z);
            Xm[(f4+3)*68 + c] = to_tf32(v.w);
        }
        __syncthreads();
        if (t < 128) {
            #pragma unroll 8
            for (int c = 0; c < 64; c++) {
                int cc = (c + t) & 63;
                cs += __uint_as_float(Xm[t*68 + cc]);
            }
        }
        #pragma unroll
        for (int ks = 0; ks < 8; ks++) {
            int k0 = ks*8 + 2*lb;
            uint2 af[2][2];
            #pragma unroll
            for (int m = 0; m < 2; m++) {
                int r0 = wi*32 + m*16 + la;
                af[m][0] = *(uint2*)(Wm + r0*68 + k0);
                af[m][1] = *(uint2*)(Wm + (r0+8)*68 + k0);
            }
            uint2 bf[4];
            #pragma unroll
            for (int n = 0; n < 4; n++) {
                int j0 = wj*32 + n*8 + la;
                bf[n] = *(uint2*)(Xm + j0*68 + k0);
            }
            #pragma unroll
            for (int m = 0; m < 2; m++)
                #pragma unroll
                for (int n = 0; n < 4; n++)
                    mma_tf32(acc[m][n], af[m][0].x, af[m][1].x,
                             af[m][0].y, af[m][1].y, bf[n].x, bf[n].y);
        }
    }
    /* reduce W row sums: threads sharing t>>4 are 16 consecutive lanes (half warp) */
    #pragma unroll
    for (int j = 0; j < 4; j++) {
        float v = wpart[j];
        v += __shfl_xor_sync(0xffffffffu, v, 1);
        v += __shfl_xor_sync(0xffffffffu, v, 2);
        v += __shfl_xor_sync(0xffffffffu, v, 4);
        v += __shfl_xor_sync(0xffffffffu, v, 8);
        wpart[j] = v;
    }
    __syncthreads();
    if ((t & 15) == 0) {
        #pragma unroll
        for (int j = 0; j < 4; j++) wsum_s[(t >> 4) + 16*j] = wpart[j];
    }
    if (t < 128) minv[t] = cs * (1.f/CIN);
    __syncthreads();

    #pragma unroll
    for (int n = 0; n < 4; n++)
        #pragma unroll
        for (int p = 0; p < 2; p++) {
            int col = wj*32 + n*8 + 2*lb + p;
            float mv = minv[col];
            float s4 = 0.f;
            #pragma unroll
            for (int m = 0; m < 2; m++)
                #pragma unroll
                for (int h = 0; h < 2; h++) {
                    int r = wi*32 + m*16 + la + 8*h;
                    float y = acc[m][n][2*h+p] - wsum_s[r]*mv;
                    y = fmaxf(fmaf(y, scale_s[r], bias_s[r]), 0.f);
                    acc[m][n][2*h+p] = y;
                    s4 = fmaf(y, y, s4);
                }
            s4 += __shfl_xor_sync(0xffffffffu, s4, 4);
            s4 += __shfl_xor_sync(0xffffffffu, s4, 8);
            s4 += __shfl_xor_sync(0xffffffffu, s4, 16);
            if (la == 0) ssqred[col*2 + wi] = s4;
        }
    __syncthreads();
    if (t < 128) {
        linv[t] = 1.f / fmaxf(sqrtf(ssqred[t*2] + ssqred[t*2+1]), L2_EPS);
        moutp[t0 + t] = minv[t];
    }
    __syncthreads();

    float* sout = (float*)pj_sm;             // [128][68]
    #pragma unroll
    for (int n = 0; n < 4; n++)
        #pragma unroll
        for (int p = 0; p < 2; p++) {
            int col = wj*32 + n*8 + 2*lb + p;
            float lv = linv[col];
            #pragma unroll
            for (int m = 0; m < 2; m++)
                #pragma unroll
                for (int h = 0; h < 2; h++) {
                    int r = wi*32 + m*16 + la + 8*h;
                    sout[col*68 + perm8(r)] = acc[m][n][2*h+p] * lv;
                }
        }
    __syncthreads();
    #pragma unroll
    for (int j = 0; j < 8; j++) {
        int idx = t + j*256;
        int col = idx >> 4, c4 = (idx & 15) << 2;
        *(float4*)(outp + (size_t)(t0 + col)*CP + c4) = *(float4*)&sout[col*68 + c4];
    }
}

/* ------------- Kgram: per batch token-mean + centered Gram (64x64) ------------- */
__global__ __launch_bounds__(256) void kgram() {
    __shared__ float Xs[128*68];
    __shared__ float abar_s[64];

    int b = blockIdx.x;
    const float* X = (b < WAY) ? g_S + (size_t)b*NTOK*CP
                               : g_Q + (size_t)(b-WAY)*NTOK*CP;
    int t = threadIdx.x;

    float csum = 0.f;
    for (int ck = 0; ck < 4; ck++) {
        for (int idx = t; idx < 128*16; idx += 256) {
            int r = idx >> 4, c4 = (idx & 15) << 2;
            *(float4*)&Xs[r*68 + c4] = *(const float4*)(X + (size_t)(ck*128 + r)*CP + c4);
        }
        __syncthreads();
        if (t < 64) {
            #pragma unroll 8
            for (int r = 0; r < 128; r++) csum += Xs[r*68 + t];
        }
        __syncthreads();
    }
    if (t < 64) {
        float m = csum * (1.f/512.f);
        abar_s[t] = m;
        g_bar[b*CP + t] = m;
    }
    __syncthreads();

    float gacc[4][4];
    #pragma unroll
    for (int i = 0; i < 4; i++)
        #pragma unroll
        for (int j = 0; j < 4; j++) gacc[i][j] = 0.f;
    int a0 = (t >> 4) * 4, b0 = (t & 15) * 4;

    for (int ck = 0; ck < 4; ck++) {
        for (int idx = t; idx < 128*16; idx += 256) {
            int r = idx >> 4, c4 = (idx & 15) << 2;
            float4 v = *(const float4*)(X + (size_t)(ck*128 + r)*CP + c4);
            v.x -= abar_s[c4+0]; v.y -= abar_s[c4+1];
            v.z -= abar_s[c4+2]; v.w -= abar_s[c4+3];
            *(float4*)&Xs[r*68 + c4] = v;
        }
        __syncthreads();
        #pragma unroll 4
        for (int r = 0; r < 128; r++) {
            float4 av = *(float4*)&Xs[r*68 + a0];
            float4 bv = *(float4*)&Xs[r*68 + b0];
            float aa[4] = {av.x, av.y, av.z, av.w};
            float bb[4] = {bv.x, bv.y, bv.z, bv.w};
            #pragma unroll
            for (int i = 0; i < 4; i++)
                #pragma unroll
                for (int j = 0; j < 4; j++)
                    gacc[i][j] = fmaf(aa[i], bb[j], gacc[i][j]);
        }
        __syncthreads();
    }
    #pragma unroll
    for (int i = 0; i < 4; i++)
        #pragma unroll
        for (int j = 0; j < 4; j++)
            g_G[(size_t)b*CP*CP + (a0+i)*CP + b0+j] = gacc[i][j];
}

/* ------------- Kpass: EXACT r8 measured-best config (256 thr, 64x64 warp tile, Ebuf) --- */
#define KP_SMEM_BYTES 231168

extern "C" __global__ void __launch_bounds__(256, 1) kpass() {
    extern __shared__ unsigned char kp_sm[];
    unsigned* Bstf = (unsigned*)kp_sm;            // [128][68] tf32
    unsigned* Astf = Bstf + 128*68;               // [128][68]
    unsigned* Gm   = Astf + 128*68;               // [64][68]
    __half*  Ebuf  = (__half*)(Gm + 64*68);       // [512][136]
    float* zred    = (float*)(Ebuf + 512*136);    // [128][5]
    float* bscale  = zred + 128*5;                // [128]
    float* bofs    = bscale + 128;
    float* bmean   = bofs + 128;
    float* zsum    = bmean + 128;
    float* abar    = zsum + 128;                  // [64]

    int bid = blockIdx.x;
    int mode = (bid >= PAIRS);
    int pair = bid - mode*PAIRS;
    int qq = pair / WAY, ww = pair % WAY;
    const float *A, *B, *Gp, *barp;
    float* outp;
    if (mode == 0) {
        A = g_S + (size_t)ww*NTOK*CP;  B = g_Q + (size_t)qq*NTOK*CP;
        Gp = g_G + (size_t)ww*CP*CP;   barp = g_bar + ww*CP;
        outp = g_as + pair*NTOK;
    } else {
        A = g_Q + (size_t)qq*NTOK*CP;  B = g_S + (size_t)ww*NTOK*CP;
        Gp = g_G + (size_t)(WAY+qq)*CP*CP;  barp = g_bar + (WAY+qq)*CP;
        outp = g_aq + pair*NTOK;
    }

    int t = threadIdx.x, lane = t & 31, warp = t >> 5;
    int wi = warp >> 1, wj = warp & 1;
    int la = lane >> 2, lb = lane & 3;

    for (int i = t; i < 64*64; i += 256)
        Gm[(i >> 6)*68 + (i & 63)] = to_tf32(Gp[i]);
    if (t < 64) abar[t] = barp[t];

    float attn0 = 0.f, attn1 = 0.f;

    for (int sb = 0; sb < 4; sb++) {
        __syncthreads();
        for (int idx = t; idx < 128*16; idx += 256) {
            int r = idx >> 4, c4 = (idx & 15) << 2;
            float4 v = *(const float4*)(B + (size_t)(sb*128 + r)*CP + c4);
            uint4 u = make_uint4(to_tf32(v.x), to_tf32(v.y), to_tf32(v.z), to_tf32(v.w));
            *(uint4*)(Bstf + r*68 + c4) = u;
        }
        if (t < 128) zsum[t] = 0.f;
        __syncthreads();

        /* stats: H = Bstf*G', 511*var_j = b_j.h_j */
        {
            float sacc[2][4][4];
            #pragma unroll
            for (int m = 0; m < 2; m++)
                #pragma unroll
                for (int n = 0; n < 4; n++)
                    #pragma unroll
                    for (int e = 0; e < 4; e++) sacc[m][n][e] = 0.f;
            #pragma unroll
            for (int ks = 0; ks < 8; ks++) {
                int k0 = ks*8 + 2*lb;
                uint2 saf[2][2];
                #pragma unroll
                for (int m = 0; m < 2; m++) {
                    int r0 = wi*32 + m*16 + la;
                    saf[m][0] = *(uint2*)(Bstf + r0*68 + k0);
                    saf[m][1] = *(uint2*)(Bstf + (r0+8)*68 + k0);
                }
                uint2 sbf[4];
                #pragma unroll
                for (int n = 0; n < 4; n++) {
                    int j0 = wj*32 + n*8 + la;
                    sbf[n] = *(uint2*)(Gm + j0*68 + k0);
                }
                #pragma unroll
                for (int m = 0; m < 2; m++)
                    #pragma unroll
                    for (int n = 0; n < 4; n++)
                        mma_tf32(sacc[m][n], saf[m][0].x, saf[m][1].x,
                                 saf[m][0].y, saf[m][1].y, sbf[n].x, sbf[n].y);
            }
            #pragma unroll
            for (int m = 0; m < 2; m++)
                #pragma unroll
                for (int h = 0; h < 2; h++) {
                    int j = wi*32 + m*16 + la + 8*h;
                    float s = 0.f;
                    #pragma unroll
                    for (int n = 0; n < 4; n++)
                        #pragma unroll
                        for (int p = 0; p < 2; p++) {
                            int ch = wj*32 + n*8 + 2*lb + p;
                            s = fmaf(sacc[m][n][2*h+p],
                                     __uint_as_float(Bstf[j*68 + ch]), s);
                        }
                    s += __shfl_xor_sync(0xffffffffu, s, 1);
                    s += __shfl_xor_sync(0xffffffffu, s, 2);
                    if (lb == 0) zred[j*5 + wj] = s;
                }
        }
        if (t < 128) {
            float m = 0.f;
            #pragma unroll 8
            for (int c = 0; c < 64; c++)
                m = fmaf(__uint_as_float(Bstf[t*68 + c]), abar[c], m);
            bmean[t] = m;
        }
        __syncthreads();
        if (t < 128) {
            float var = (zred[t*5] + zred[t*5+1]) * (1.f/511.f);
            float sc = LOG2E / (5.f * sqrtf(var + GN_EPS));
            bscale[t] = sc;
            bofs[t] = bmean[t] * sc;
        }
        __syncthreads();

        float cs[16], co[16];
        #pragma unroll
        for (int n = 0; n < 8; n++)
            #pragma unroll
            for (int p = 0; p < 2; p++) {
                int col = wj*64 + n*8 + 2*lb + p;
                cs[2*n+p] = bscale[col];
                co[2*n+p] = bofs[col];
            }

        for (int ab = 0; ab < 4; ab++) {
            __syncthreads();
            for (int idx = t; idx < 128*16; idx += 256) {
                int r = idx >> 4, c4 = (idx & 15) << 2;
                float4 v = *(const float4*)(A + (size_t)(ab*128 + r)*CP + c4);
                uint4 u = make_uint4(to_tf32(v.x), to_tf32(v.y), to_tf32(v.z), to_tf32(v.w));
                *(uint4*)(Astf + r*68 + c4) = u;
            }
            __syncthreads();

            float acc[2][8][4];
            #pragma unroll
            for (int m = 0; m < 2; m++)
                #pragma unroll
                for (int n = 0; n < 8; n++)
                    #pragma unroll
                    for (int e = 0; e < 4; e++) acc[m][n][e] = 0.f;

            #pragma unroll
            for (int ks = 0; ks < 8; ks++) {
                int k0 = ks*8 + 2*lb;
                uint2 af[2][2];
                #pragma unroll
                for (int m = 0; m < 2; m++) {
                    int r0 = wi*32 + m*16 + la;
                    af[m][0] = *(uint2*)(Astf + r0*68 + k0);
                    af[m][1] = *(uint2*)(Astf + (r0+8)*68 + k0);
                }
                uint2 bf[8];
                #pragma unroll
                for (int n = 0; n < 8; n++) {
                    int j0 = wj*64 + n*8 + la;
                    bf[n] = *(uint2*)(Bstf + j0*68 + k0);
                }
                #pragma unroll
                for (int m = 0; m < 2; m++)
                    #pragma unroll
                    for (int n = 0; n < 8; n++)
                        mma_tf32(acc[m][n], af[m][0].x, af[m][1].x,
                                 af[m][0].y, af[m][1].y, bf[n].x, bf[n].y);
            }

            float zp[16];
            #pragma unroll
            for (int i = 0; i < 16; i++) zp[i] = 0.f;
            #pragma unroll
            for (int m = 0; m < 2; m++)
                #pragma unroll
                for (int h = 0; h < 2; h++) {
                    int arow = ab*128 + wi*32 + m*16 + la + 8*h;
                    __half* erow = Ebuf + arow*136 + wj*64;
                    #pragma unroll
                    for (int n = 0; n < 8; n++) {
                        float e0 = ex2(fmaf(acc[m][n][2*h+0], cs[2*n+0], -co[2*n+0]));
                        float e1 = ex2(fmaf(acc[m][n][2*h+1], cs[2*n+1], -co[2*n+1]));
                        zp[2*n+0] += e0;
                        zp[2*n+1] += e1;
                        *(__half2*)(erow + n*8 + 2*lb) = __floats2half2_rn(e0, e1);
                    }
                }
            #pragma unroll
            for (int n = 0; n < 8; n++)
                #pragma unroll
                for (int p = 0; p < 2; p++) {
                    float v = zp[2*n+p];
                    v += __shfl_xor_sync(0xffffffffu, v, 4);
                    v += __shfl_xor_sync(0xffffffffu, v, 8);
                    v += __shfl_xor_sync(0xffffffffu, v, 16);
                    if (la == 0)
                        zred[(wj*64 + n*8 + 2*lb + p)*5 + wi] = v;
                }
            __syncthreads();
            if (t < 128)
                zsum[t] += zred[t*5] + zred[t*5+1] + zred[t*5+2] + zred[t*5+3];
        }
        __syncthreads();
        if (t < 128) zsum[t] = 1.f / zsum[t];
        __syncthreads();

        {
            const __half* r0p = Ebuf + t*136;
            const __half* r1p = Ebuf + (t+256)*136;
            #pragma unroll 4
            for (int jj = 0; jj < 16; jj++) {
                uint4 e0 = *(const uint4*)(r0p + jj*8);
                uint4 e1 = *(const uint4*)(r1p + jj*8);
                const __half2* h0 = (const __half2*)&e0;
                const __half2* h1 = (const __half2*)&e1;
                #pragma unroll
                for (int u = 0; u < 4; u++) {
                    float2 f0 = __half22float2(h0[u]);
                    float2 f1 = __half22float2(h1[u]);
                    int c = jj*8 + u*2;
                    float rz0 = zsum[c], rz1 = zsum[c+1];
                    attn0 = fmaf(f0.x, rz0, attn0);
                    attn0 = fmaf(f0.y, rz1, attn0);
                    attn1 = fmaf(f1.x, rz0, attn1);
                    attn1 = fmaf(f1.y, rz1, attn1);
                }
            }
        }
    }
    outp[t] = attn0;
    outp[t + 256] = attn1;
}

/* ------------- Kpool (merged): bid<50 -> S-pool role, else Q-pool role ------------- */
#define PS_SMEM ((64*129 + 75*128) * 4)   /* 71424 B */

__global__ __launch_bounds__(256) void kpool(const float* __restrict__ sup,
                                             const float* __restrict__ qry) {
    extern __shared__ float ps_sm[];
    int t = threadIdx.x;

    if (blockIdx.x < WAY*10) {
        /* ---- S role: pooled_s[q][w][c-tile] for all 75 q ---- */
        float* xs  = ps_sm;              // [64][129]
        float* asb = ps_sm + 64*129;     // [75][128]
        int w = blockIdx.x / 10, ct = blockIdx.x % 10;
        int c0 = ct*64;
        int c = t & 63, qb = t >> 6;
        const float* X = sup + (size_t)w*CIN*NTOK + (size_t)c0*NTOK;

        float acc[19];
        #pragma unroll
        for (int j = 0; j < 19; j++) acc[j] = 0.f;

        for (int i0 = 0; i0 < NTOK; i0 += 128) {
            __syncthreads();
            for (int idx = t; idx < 64*32; idx += 256) {
                int r = idx >> 5, i4 = (idx & 31) << 2;
                float4 v = *(const float4*)(X + (size_t)r*NTOK + i0 + i4);
                xs[r*129 + i4+0] = v.x; xs[r*129 + i4+1] = v.y;
                xs[r*129 + i4+2] = v.z; xs[r*129 + i4+3] = v.w;
            }
            for (int idx = t; idx < 75*32; idx += 256) {
                int r = idx / 32, i4 = (idx & 31) << 2;
                *(float4*)&asb[r*128 + i4] =
                    *(const float4*)(g_as + (size_t)(r*WAY + w)*NTOK + i0 + i4);
            }
            __syncthreads();
            for (int i = 0; i < 128; i += 4) {
                float x0 = xs[c*129 + i],   x1 = xs[c*129 + i+1];
                float x2 = xs[c*129 + i+2], x3 = xs[c*129 + i+3];
                #pragma unroll
                for (int j = 0; j < 19; j++) {
                    int q = qb + 4*j;
                    if (q < NQ) {
                        float4 a = *(float4*)&asb[q*128 + i];
                        acc[j] = fmaf(a.x, x0, fmaf(a.y, x1, fmaf(a.z, x2, fmaf(a.w, x3, acc[j]))));
                    }
                }
            }
        }
        #pragma unroll
        for (int j = 0; j < 19; j++) {
            int q = qb + 4*j;
            if (q < NQ) g_ps[(size_t)(q*WAY + w)*CIN + c0 + c] = acc[j];
        }
    } else {
        /* ---- Q role: pooled_q[q][w][c-tile] for the 5 ways ---- */
        float* xs  = ps_sm;              // [64][129]
        float* aqb = ps_sm + 64*129;     // [5][128]
        float* red = aqb + 5*128;        // [5*64][4]
        int bidq = blockIdx.x - WAY*10;
        int q = bidq / 10, ct = bidq % 10;
        int c0 = ct*64;
        int c = t & 63, g = t >> 6;
        const float* X = qry + (size_t)q*CIN*NTOK + (size_t)c0*NTOK;

        float acc[5] = {0.f, 0.f, 0.f, 0.f, 0.f};

        for (int i0 = 0; i0 < NTOK; i0 += 128) {
            __syncthreads();
            for (int idx = t; idx < 64*32; idx += 256) {
                int r = idx >> 5, i4 = (idx & 31) << 2;
                float4 v = *(const float4*)(X + (size_t)r*NTOK + i0 + i4);
                xs[r*129 + i4+0] = v.x; xs[r*129 + i4+1] = v.y;
                xs[r*129 + i4+2] = v.z; xs[r*129 + i4+3] = v.w;
            }
            for (int idx = t; idx < 5*32; idx += 256) {
                int r = idx / 32, i4 = (idx & 31) << 2;
                *(float4*)&aqb[r*128 + i4] =
                    *(const float4*)(g_aq + (size_t)(q*WAY + r)*NTOK + i0 + i4);
            }
            __syncthreads();
            for (int i = g*32; i < g*32 + 32; i += 4) {
                float x0 = xs[c*129 + i],   x1 = xs[c*129 + i+1];
                float x2 = xs[c*129 + i+2], x3 = xs[c*129 + i+3];
                #pragma unroll
                for (int wv = 0; wv < 5; wv++) {
                    float4 a = *(float4*)&aqb[wv*128 + i];
                    acc[wv] = fmaf(a.x, x0, fmaf(a.y, x1, fmaf(a.z, x2, fmaf(a.w, x3, acc[wv]))));
                }
            }
        }
        #pragma unroll
        for (int wv = 0; wv < 5; wv++) red[(wv*64 + c)*4 + g] = acc[wv];
        __syncthreads();
        for (int idx = t; idx < 5*64; idx += 256) {
            int wv = idx >> 6, cc = idx & 63;
            float s = red[idx*4] + red[idx*4+1] + red[idx*4+2] + red[idx*4+3];
            g_pq[(size_t)(q*WAY + wv)*CIN + c0 + cc] = s;
        }
    }
}

/* ------------- Kcos: mean corrections + cosine sim ------------- */
__global__ __launch_bounds__(128) void kcos(float* __restrict__ out) {
    __shared__ float rbuf[4*5];
    int pair = blockIdx.x, q = pair / WAY, w = pair % WAY;
    int t = threadIdx.x, lane = t & 31, wp = t >> 5;

    float cS = 0.f, cQ = 0.f;
    for (int i = t; i < NTOK; i += 128) {
        cS = fmaf(g_as[pair*NTOK + i], g_mS[w*NTOK + i], cS);
        cQ = fmaf(g_aq[pair*NTOK + i], g_mQ[q*NTOK + i], cQ);
    }
    cS = warp_sum(cS); cQ = warp_sum(cQ);
    if (lane == 0) { rbuf[wp*5+0] = cS; rbuf[wp*5+1] = cQ; }
    __syncthreads();
    cS = rbuf[0] + rbuf[5] + rbuf[10] + rbuf[15];
    cQ = rbuf[1] + rbuf[6] + rbuf[11] + rbuf[16];
    __syncthreads();

    float dp = 0.f, ns = 0.f, nq2 = 0.f;
    for (int c = t; c < CIN; c += 128) {
        float a = g_ps[(size_t)pair*CIN + c] - cS;
        float b = g_pq[(size_t)pair*CIN + c] - cQ;
        dp = fmaf(a, b, dp); ns = fmaf(a, a, ns); nq2 = fmaf(b, b, nq2);
    }
    dp = warp_sum(dp); ns = warp_sum(ns); nq2 = warp_sum(nq2);
    if (lane == 0) { rbuf[wp*5+0] = dp; rbuf[wp*5+1] = ns; rbuf[wp*5+2] = nq2; }
    __syncthreads();
    if (t == 0) {
        dp  = rbuf[0] + rbuf[5] + rbuf[10] + rbuf[15];
        ns  = rbuf[1] + rbuf[6] + rbuf[11] + rbuf[16];
        nq2 = rbuf[2] + rbuf[7] + rbuf[12] + rbuf[17];
        float psn = fmaxf(sqrtf(ns)  * (1.f/512.f), L2_EPS);
        float pqn = fmaxf(sqrtf(nq2) * (1.f/512.f), L2_EPS);
        out[pair] = (dp * (1.f/(512.f*512.f))) / (psn * pqn) * 5.f;
    }
}

/* ------------- launcher ------------- */
extern "C" void kernel_launch(void* const* d_in, const int* in_sizes, int n_in,
                              void* d_out, int out_size) {
    const float* sup   = (const float*)d_in[0];
    const float* qry   = (const float*)d_in[1];
    const float* W     = (const float*)d_in[2];
    const float* gamma = (const float*)d_in[3];
    const float* beta  = (const float*)d_in[4];
    const float* mean  = (const float*)d_in[5];
    const float* var   = (const float*)d_in[6];
    float* out = (float*)d_out;

    cudaFuncSetAttribute(kpass, cudaFuncAttributeMaxDynamicSharedMemorySize, KP_SMEM_BYTES);
    cudaFuncSetAttribute(kproj, cudaFuncAttributeMaxDynamicSharedMemorySize, PJ_SMEM);
    cudaFuncSetAttribute(kpool, cudaFuncAttributeMaxDynamicSharedMemorySize, PS_SMEM);

    kproj<<<(WAY+NQ)*4, 256, PJ_SMEM>>>(sup, qry, W, gamma, beta, mean, var);
    kgram<<<WAY+NQ, 256>>>();
    kpass<<<2*PAIRS, 256, KP_SMEM_BYTES>>>();
    kpool<<<WAY*10 + NQ*10, 256, PS_SMEM>>>(sup, qry);
    kcos<<<PAIRS, 128>>>(out);
}

// round 17
// speedup vs baseline: 1.1002x; 1.0021x over previous
#include <cuda_runtime.h>
#include <cuda_fp16.h>
#include <cuda_bf16.h>

#define WAY   5
#define NQ    75
#define CIN   640
#define NTOK  512
#define CP    64
#define PAIRS (WAY*NQ)          /* 375 */
#define BN_EPS 1e-5f
#define GN_EPS 1e-5f
#define L2_EPS 1e-8f
#define LOG2E  1.4426950408889634f

/* scratch (device globals)
 * g_S/g_Q: [batch][tok 512][ch 64], channels PERMUTED by perm8() */
__device__ float g_S[WAY*NTOK*CP];
__device__ float g_Q[NQ*NTOK*CP];
__device__ float g_mS[WAY*NTOK];
__device__ float g_mQ[NQ*NTOK];
__device__ float g_G[(WAY+NQ)*CP*CP];
__device__ float g_bar[(WAY+NQ)*CP];
__device__ float g_as[PAIRS*NTOK];
__device__ float g_aq[PAIRS*NTOK];
__device__ float g_ps[PAIRS*CIN];
__device__ float g_pq[PAIRS*CIN];

__device__ __forceinline__ float ex2(float x) {
    float y;
    asm("ex2.approx.ftz.f32 %0, %1;" : "=f"(y) : "f"(x));
    return y;
}
__device__ __forceinline__ float warp_sum(float v) {
    #pragma unroll
    for (int o = 16; o; o >>= 1) v += __shfl_xor_sync(0xffffffffu, v, o);
    return v;
}
__device__ __forceinline__ unsigned to_tf32(float f) {
    unsigned u;
    asm("cvt.rna.tf32.f32 %0, %1;" : "=r"(u) : "f"(f));
    return u;
}
__device__ __forceinline__ int perm8(int c) {
    return (c & ~7) | ((c & 3) * 2) | ((c >> 2) & 1);
}
__device__ __forceinline__ void mma_tf32(float* d, unsigned a0, unsigned a1,
                                         unsigned a2, unsigned a3,
                                         unsigned b0, unsigned b1) {
    asm volatile(
        "mma.sync.aligned.m16n8k8.row.col.f32.tf32.tf32.f32 "
        "{%0,%1,%2,%3}, {%4,%5,%6,%7}, {%8,%9}, {%0,%1,%2,%3};"
        : "+f"(d[0]), "+f"(d[1]), "+f"(d[2]), "+f"(d[3])
        : "r"(a0), "r"(a1), "r"(a2), "r"(a3), "r"(b0), "r"(b1));
}

/* ------------- K0 (tf32 mma): projection -> transposed+permuted [tok][64] -------------
 * kpre folded in: each CTA computes wsum/scale/bias itself (it reads all of W anyway).
 */
#define PJ_SMEM (64*68*4 + 128*68*4 + (64*3 + 128 + 128*2 + 128)*4)   /* 55040 B */

__global__ void __launch_bounds__(256, 2) kproj(const float* __restrict__ sup,
                                                const float* __restrict__ qry,
                                                const float* __restrict__ W,
                                                const float* __restrict__ gamma,
                                                const float* __restrict__ beta,
                                                const float* __restrict__ mean,
                                                const float* __restrict__ var) {
    extern __shared__ unsigned pj_sm[];
    unsigned* Wm = pj_sm;                    // [64][68] tf32
    unsigned* Xm = Wm + 64*68;               // [128][68] tf32 (x transposed)
    float* wsum_s  = (float*)(Xm + 128*68);  // [64]
    float* scale_s = wsum_s + 64;
    float* bias_s  = scale_s + 64;
    float* minv    = bias_s + 64;            // [128]
    float* ssqred  = minv + 128;             // [128][2]
    float* linv    = ssqred + 256;           // [128]

    int b  = blockIdx.x >> 2;
    int t0 = (blockIdx.x & 3) * 128;
    const float* x  = (b < WAY) ? sup + (size_t)b*CIN*NTOK : qry + (size_t)(b-WAY)*CIN*NTOK;
    float* outp     = (b < WAY) ? g_S + b*NTOK*CP          : g_Q + (b-WAY)*NTOK*CP;
    float* moutp    = (b < WAY) ? g_mS + b*NTOK            : g_mQ + (b-WAY)*NTOK;

    int t = threadIdx.x, lane = t & 31, warp = t >> 5;
    int wi = warp >> 2, wj = warp & 3;
    int la = lane >> 2, lb = lane & 3;

    if (t < 64) {
        float sc = gamma[t] * rsqrtf(var[t] + BN_EPS);
        scale_s[t] = sc;
        bias_s[t]  = beta[t] - mean[t] * sc;
    }

    float acc[2][4][4];
    #pragma unroll
    for (int m = 0; m < 2; m++)
        #pragma unroll
        for (int n = 0; n < 4; n++)
            #pragma unroll
            for (int e = 0; e < 4; e++) acc[m][n][e] = 0.f;
    float cs = 0.f;
    float wpart[4] = {0.f, 0.f, 0.f, 0.f};   /* W row-sum partials (row = t>>4 + 16j) */

    for (int ch = 0; ch < 10; ch++) {
        __syncthreads();
        #pragma unroll
        for (int j = 0; j < 4; j++) {
            int idx = t + j*256;
            int o = idx >> 4, c4 = (idx & 15) << 2;
            float4 v = *(const float4*)(W + (size_t)o*CIN + ch*64 + c4);
            wpart[j] += v.x + v.y + v.z + v.w;
            *(uint4*)(Wm + o*68 + c4) =
                make_uint4(to_tf32(v.x), to_tf32(v.y), to_tf32(v.z), to_tf32(v.w));
        }
        #pragma unroll
        for (int it = 0; it < 8; it++) {
            int fidx = t + it*256;
            int c = fidx >> 5, f4 = (fidx & 31) << 2;
            float4 v = *(const float4*)(x + (size_t)(ch*64 + c)*NTOK + t0 + f4);
            Xm[(f4+0)*68 + c] = to_tf32(v.x);
            Xm[(f4+1)*68 + c] = to_tf32(v.y);
            Xm[(f4+2)*68 + c] = to_tf32(v.z);
            Xm[(f4+3)*68 + c] = to_tf32(v.w);
        }
        __syncthreads();
        if (t < 128) {
            #pragma unroll 8
            for (int c = 0; c < 64; c++) {
                int cc = (c + t) & 63;
                cs += __uint_as_float(Xm[t*68 + cc]);
            }
        }
        #pragma unroll
        for (int ks = 0; ks < 8; ks++) {
            int k0 = ks*8 + 2*lb;
            uint2 af[2][2];
            #pragma unroll
            for (int m = 0; m < 2; m++) {
                int r0 = wi*32 + m*16 + la;
                af[m][0] = *(uint2*)(Wm + r0*68 + k0);
                af[m][1] = *(uint2*)(Wm + (r0+8)*68 + k0);
            }
            uint2 bf[4];
            #pragma unroll
            for (int n = 0; n < 4; n++) {
                int j0 = wj*32 + n*8 + la;
                bf[n] = *(uint2*)(Xm + j0*68 + k0);
            }
            #pragma unroll
            for (int m = 0; m < 2; m++)
                #pragma unroll
                for (int n = 0; n < 4; n++)
                    mma_tf32(acc[m][n], af[m][0].x, af[m][1].x,
                             af[m][0].y, af[m][1].y, bf[n].x, bf[n].y);
        }
    }
    /* reduce W row sums: threads sharing t>>4 are 16 consecutive lanes (half warp) */
    #pragma unroll
    for (int j = 0; j < 4; j++) {
        float v = wpart[j];
        v += __shfl_xor_sync(0xffffffffu, v, 1);
        v += __shfl_xor_sync(0xffffffffu, v, 2);
        v += __shfl_xor_sync(0xffffffffu, v, 4);
        v += __shfl_xor_sync(0xffffffffu, v, 8);
        wpart[j] = v;
    }
    __syncthreads();
    if ((t & 15) == 0) {
        #pragma unroll
        for (int j = 0; j < 4; j++) wsum_s[(t >> 4) + 16*j] = wpart[j];
    }
    if (t < 128) minv[t] = cs * (1.f/CIN);
    __syncthreads();

    #pragma unroll
    for (int n = 0; n < 4; n++)
        #pragma unroll
        for (int p = 0; p < 2; p++) {
            int col = wj*32 + n*8 + 2*lb + p;
            float mv = minv[col];
            float s4 = 0.f;
            #pragma unroll
            for (int m = 0; m < 2; m++)
                #pragma unroll
                for (int h = 0; h < 2; h++) {
                    int r = wi*32 + m*16 + la + 8*h;
                    float y = acc[m][n][2*h+p] - wsum_s[r]*mv;
                    y = fmaxf(fmaf(y, scale_s[r], bias_s[r]), 0.f);
                    acc[m][n][2*h+p] = y;
                    s4 = fmaf(y, y, s4);
                }
            s4 += __shfl_xor_sync(0xffffffffu, s4, 4);
            s4 += __shfl_xor_sync(0xffffffffu, s4, 8);
            s4 += __shfl_xor_sync(0xffffffffu, s4, 16);
            if (la == 0) ssqred[col*2 + wi] = s4;
        }
    __syncthreads();
    if (t < 128) {
        linv[t] = 1.f / fmaxf(sqrtf(ssqred[t*2] + ssqred[t*2+1]), L2_EPS);
        moutp[t0 + t] = minv[t];
    }
    __syncthreads();

    float* sout = (float*)pj_sm;             // [128][68]
    #pragma unroll
    for (int n = 0; n < 4; n++)
        #pragma unroll
        for (int p = 0; p < 2; p++) {
            int col = wj*32 + n*8 + 2*lb + p;
            float lv = linv[col];
            #pragma unroll
            for (int m = 0; m < 2; m++)
                #pragma unroll
                for (int h = 0; h < 2; h++) {
                    int r = wi*32 + m*16 + la + 8*h;
                    sout[col*68 + perm8(r)] = acc[m][n][2*h+p] * lv;
                }
        }
    __syncthreads();
    #pragma unroll
    for (int j = 0; j < 8; j++) {
        int idx = t + j*256;
        int col = idx >> 4, c4 = (idx & 15) << 2;
        *(float4*)(outp + (size_t)(t0 + col)*CP + c4) = *(float4*)&sout[col*68 + c4];
    }
}

/* ------------- Kgram: per batch token-mean + centered Gram (64x64) ------------- */
__global__ __launch_bounds__(256) void kgram() {
    __shared__ float Xs[128*68];
    __shared__ float abar_s[64];

    int b = blockIdx.x;
    const float* X = (b < WAY) ? g_S + (size_t)b*NTOK*CP
                               : g_Q + (size_t)(b-WAY)*NTOK*CP;
    int t = threadIdx.x;

    float csum = 0.f;
    for (int ck = 0; ck < 4; ck++) {
        for (int idx = t; idx < 128*16; idx += 256) {
            int r = idx >> 4, c4 = (idx & 15) << 2;
            *(float4*)&Xs[r*68 + c4] = *(const float4*)(X + (size_t)(ck*128 + r)*CP + c4);
        }
        __syncthreads();
        if (t < 64) {
            #pragma unroll 8
            for (int r = 0; r < 128; r++) csum += Xs[r*68 + t];
        }
        __syncthreads();
    }
    if (t < 64) {
        float m = csum * (1.f/512.f);
        abar_s[t] = m;
        g_bar[b*CP + t] = m;
    }
    __syncthreads();

    float gacc[4][4];
    #pragma unroll
    for (int i = 0; i < 4; i++)
        #pragma unroll
        for (int j = 0; j < 4; j++) gacc[i][j] = 0.f;
    int a0 = (t >> 4) * 4, b0 = (t & 15) * 4;

    for (int ck = 0; ck < 4; ck++) {
        for (int idx = t; idx < 128*16; idx += 256) {
            int r = idx >> 4, c4 = (idx & 15) << 2;
            float4 v = *(const float4*)(X + (size_t)(ck*128 + r)*CP + c4);
            v.x -= abar_s[c4+0]; v.y -= abar_s[c4+1];
            v.z -= abar_s[c4+2]; v.w -= abar_s[c4+3];
            *(float4*)&Xs[r*68 + c4] = v;
        }
        __syncthreads();
        #pragma unroll 4
        for (int r = 0; r < 128; r++) {
            float4 av = *(float4*)&Xs[r*68 + a0];
            float4 bv = *(float4*)&Xs[r*68 + b0];
            float aa[4] = {av.x, av.y, av.z, av.w};
            float bb[4] = {bv.x, bv.y, bv.z, bv.w};
            #pragma unroll
            for (int i = 0; i < 4; i++)
                #pragma unroll
                for (int j = 0; j < 4; j++)
                    gacc[i][j] = fmaf(aa[i], bb[j], gacc[i][j]);
        }
        __syncthreads();
    }
    #pragma unroll
    for (int i = 0; i < 4; i++)
        #pragma unroll
        for (int j = 0; j < 4; j++)
            g_G[(size_t)b*CP*CP + (a0+i)*CP + b0+j] = gacc[i][j];
}

/* ------------- Kpass: r8 tiling + barrier-reduced/overlapped phase schedule -----------
 * Changes vs measured r8: (1) B(sb+1) staged during attn(sb) region (zsum double-
 * buffered), (2) per-ab zsum+= folded into next ab's staging region, (3) final
 * zsum+= and 1/z merged. Tile shapes, mma layout, Ebuf identical.
 */
#define KP_SMEM_BYTES 231680

extern "C" __global__ void __launch_bounds__(256, 1) kpass() {
    extern __shared__ unsigned char kp_sm[];
    unsigned* Bstf = (unsigned*)kp_sm;            // [128][68] tf32
    unsigned* Astf = Bstf + 128*68;               // [128][68]
    unsigned* Gm   = Astf + 128*68;               // [64][68]
    __half*  Ebuf  = (__half*)(Gm + 64*68);       // [512][136]
    float* zred    = (float*)(Ebuf + 512*136);    // [128][5]
    float* bscale  = zred + 128*5;                // [128]
    float* bofs    = bscale + 128;
    float* bmean   = bofs + 128;
    float* zsumb   = bmean + 128;                 // [2][128]
    float* abar    = zsumb + 256;                 // [64]

    int bid = blockIdx.x;
    int mode = (bid >= PAIRS);
    int pair = bid - mode*PAIRS;
    int qq = pair / WAY, ww = pair % WAY;
    const float *A, *B, *Gp, *barp;
    float* outp;
    if (mode == 0) {
        A = g_S + (size_t)ww*NTOK*CP;  B = g_Q + (size_t)qq*NTOK*CP;
        Gp = g_G + (size_t)ww*CP*CP;   barp = g_bar + ww*CP;
        outp = g_as + pair*NTOK;
    } else {
        A = g_Q + (size_t)qq*NTOK*CP;  B = g_S + (size_t)ww*NTOK*CP;
        Gp = g_G + (size_t)(WAY+qq)*CP*CP;  barp = g_bar + (WAY+qq)*CP;
        outp = g_aq + pair*NTOK;
    }

    int t = threadIdx.x, lane = t & 31, warp = t >> 5;
    int wi = warp >> 1, wj = warp & 1;
    int la = lane >> 2, lb = lane & 3;

    /* prologue: Gm + abar + B(0) + zsum buffer 0 */
    for (int i = t; i < 64*64; i += 256)
        Gm[(i >> 6)*68 + (i & 63)] = to_tf32(Gp[i]);
    if (t < 64) abar[t] = barp[t];
    for (int idx = t; idx < 128*16; idx += 256) {
        int r = idx >> 4, c4 = (idx & 15) << 2;
        float4 v = *(const float4*)(B + (size_t)r*CP + c4);
        uint4 u = make_uint4(to_tf32(v.x), to_tf32(v.y), to_tf32(v.z), to_tf32(v.w));
        *(uint4*)(Bstf + r*68 + c4) = u;
    }
    if (t < 128) zsumb[t] = 0.f;
    __syncthreads();

    float attn0 = 0.f, attn1 = 0.f;

    for (int sb = 0; sb < 4; sb++) {
        float* zs = zsumb + (sb & 1)*128;

        /* stats: H = Bstf*G', 511*var_j = b_j.h_j */
        {
            float sacc[2][4][4];
            #pragma unroll
            for (int m = 0; m < 2; m++)
                #pragma unroll
                for (int n = 0; n < 4; n++)
                    #pragma unroll
                    for (int e = 0; e < 4; e++) sacc[m][n][e] = 0.f;
            #pragma unroll
            for (int ks = 0; ks < 8; ks++) {
                int k0 = ks*8 + 2*lb;
                uint2 saf[2][2];
                #pragma unroll
                for (int m = 0; m < 2; m++) {
                    int r0 = wi*32 + m*16 + la;
                    saf[m][0] = *(uint2*)(Bstf + r0*68 + k0);
                    saf[m][1] = *(uint2*)(Bstf + (r0+8)*68 + k0);
                }
                uint2 sbf[4];
                #pragma unroll
                for (int n = 0; n < 4; n++) {
                    int j0 = wj*32 + n*8 + la;
                    sbf[n] = *(uint2*)(Gm + j0*68 + k0);
                }
                #pragma unroll
                for (int m = 0; m < 2; m++)
                    #pragma unroll
                    for (int n = 0; n < 4; n++)
                        mma_tf32(sacc[m][n], saf[m][0].x, saf[m][1].x,
                                 saf[m][0].y, saf[m][1].y, sbf[n].x, sbf[n].y);
            }
            #pragma unroll
            for (int m = 0; m < 2; m++)
                #pragma unroll
                for (int h = 0; h < 2; h++) {
                    int j = wi*32 + m*16 + la + 8*h;
                    float s = 0.f;
                    #pragma unroll
                    for (int n = 0; n < 4; n++)
                        #pragma unroll
                        for (int p = 0; p < 2; p++) {
                            int ch = wj*32 + n*8 + 2*lb + p;
                            s = fmaf(sacc[m][n][2*h+p],
                                     __uint_as_float(Bstf[j*68 + ch]), s);
                        }
                    s += __shfl_xor_sync(0xffffffffu, s, 1);
                    s += __shfl_xor_sync(0xffffffffu, s, 2);
                    if (lb == 0) zred[j*5 + wj] = s;
                }
        }
        if (t < 128) {
            float m = 0.f;
            #pragma unroll 8
            for (int c = 0; c < 64; c++)
                m = fmaf(__uint_as_float(Bstf[t*68 + c]), abar[c], m);
            bmean[t] = m;
        }
        __syncthreads();
        if (t < 128) {
            float var = (zred[t*5] + zred[t*5+1]) * (1.f/511.f);
            float sc = LOG2E / (5.f * sqrtf(var + GN_EPS));
            bscale[t] = sc;
            bofs[t] = bmean[t] * sc;
        }
        __syncthreads();

        float cs[16], co[16];
        #pragma unroll
        for (int n = 0; n < 8; n++)
            #pragma unroll
            for (int p = 0; p < 2; p++) {
                int col = wj*64 + n*8 + 2*lb + p;
                cs[2*n+p] = bscale[col];
                co[2*n+p] = bofs[col];
            }

        for (int ab = 0; ab < 4; ab++) {
            __syncthreads();   /* Astf free of prior mma readers; zred(prev ab) ready */
            for (int idx = t; idx < 128*16; idx += 256) {
                int r = idx >> 4, c4 = (idx & 15) << 2;
                float4 v = *(const float4*)(A + (size_t)(ab*128 + r)*CP + c4);
                uint4 u = make_uint4(to_tf32(v.x), to_tf32(v.y), to_tf32(v.z), to_tf32(v.w));
                *(uint4*)(Astf + r*68 + c4) = u;
            }
            if (ab > 0 && t < 128)
                zs[t] += zred[t*5] + zred[t*5+1] + zred[t*5+2] + zred[t*5+3];
            __syncthreads();

            float acc[2][8][4];
            #pragma unroll
            for (int m = 0; m < 2; m++)
                #pragma unroll
                for (int n = 0; n < 8; n++)
                    #pragma unroll
                    for (int e = 0; e < 4; e++) acc[m][n][e] = 0.f;

            #pragma unroll
            for (int ks = 0; ks < 8; ks++) {
                int k0 = ks*8 + 2*lb;
                uint2 af[2][2];
                #pragma unroll
                for (int m = 0; m < 2; m++) {
                    int r0 = wi*32 + m*16 + la;
                    af[m][0] = *(uint2*)(Astf + r0*68 + k0);
                    af[m][1] = *(uint2*)(Astf + (r0+8)*68 + k0);
                }
                uint2 bf[8];
                #pragma unroll
                for (int n = 0; n < 8; n++) {
                    int j0 = wj*64 + n*8 + la;
                    bf[n] = *(uint2*)(Bstf + j0*68 + k0);
                }
                #pragma unroll
                for (int m = 0; m < 2; m++)
                    #pragma unroll
                    for (int n = 0; n < 8; n++)
                        mma_tf32(acc[m][n], af[m][0].x, af[m][1].x,
                                 af[m][0].y, af[m][1].y, bf[n].x, bf[n].y);
            }

            float zp[16];
            #pragma unroll
            for (int i = 0; i < 16; i++) zp[i] = 0.f;
            #pragma unroll
            for (int m = 0; m < 2; m++)
                #pragma unroll
                for (int h = 0; h < 2; h++) {
                    int arow = ab*128 + wi*32 + m*16 + la + 8*h;
                    __half* erow = Ebuf + arow*136 + wj*64;
                    #pragma unroll
                    for (int n = 0; n < 8; n++) {
                        float e0 = ex2(fmaf(acc[m][n][2*h+0], cs[2*n+0], -co[2*n+0]));
                        float e1 = ex2(fmaf(acc[m][n][2*h+1], cs[2*n+1], -co[2*n+1]));
                        zp[2*n+0] += e0;
                        zp[2*n+1] += e1;
                        *(__half2*)(erow + n*8 + 2*lb) = __floats2half2_rn(e0, e1);
                    }
                }
            #pragma unroll
            for (int n = 0; n < 8; n++)
                #pragma unroll
                for (int p = 0; p < 2; p++) {
                    float v = zp[2*n+p];
                    v += __shfl_xor_sync(0xffffffffu, v, 4);
                    v += __shfl_xor_sync(0xffffffffu, v, 8);
                    v += __shfl_xor_sync(0xffffffffu, v, 16);
                    if (la == 0)
                        zred[(wj*64 + n*8 + 2*lb + p)*5 + wi] = v;
                }
        }
        __syncthreads();
        if (t < 128) {
            float z = zs[t] + zred[t*5] + zred[t*5+1] + zred[t*5+2] + zred[t*5+3];
            zs[t] = 1.f / z;
        }
        __syncthreads();

        /* attn(sb) overlapped with B(sb+1) staging (no barrier between) */
        {
            const __half* r0p = Ebuf + t*136;
            const __half* r1p = Ebuf + (t+256)*136;
            #pragma unroll 4
            for (int jj = 0; jj < 16; jj++) {
                uint4 e0 = *(const uint4*)(r0p + jj*8);
                uint4 e1 = *(const uint4*)(r1p + jj*8);
                const __half2* h0 = (const __half2*)&e0;
                const __half2* h1 = (const __half2*)&e1;
                #pragma unroll
                for (int u = 0; u < 4; u++) {
                    float2 f0 = __half22float2(h0[u]);
                    float2 f1 = __half22float2(h1[u]);
                    int c = jj*8 + u*2;
                    float rz0 = zs[c], rz1 = zs[c+1];
                    attn0 = fmaf(f0.x, rz0, attn0);
                    attn0 = fmaf(f0.y, rz1, attn0);
                    attn1 = fmaf(f1.x, rz0, attn1);
                    attn1 = fmaf(f1.y, rz1, attn1);
                }
            }
        }
        if (sb < 3) {
            for (int idx = t; idx < 128*16; idx += 256) {
                int r = idx >> 4, c4 = (idx & 15) << 2;
                float4 v = *(const float4*)(B + (size_t)((sb+1)*128 + r)*CP + c4);
                uint4 u = make_uint4(to_tf32(v.x), to_tf32(v.y), to_tf32(v.z), to_tf32(v.w));
                *(uint4*)(Bstf + r*68 + c4) = u;
            }
            if (t < 128) zsumb[((sb+1) & 1)*128 + t] = 0.f;
        }
        __syncthreads();
    }
    outp[t] = attn0;
    outp[t + 256] = attn1;
}

/* ------------- Kpool (merged): bid<50 -> S-pool role, else Q-pool role ------------- */
#define PS_SMEM ((64*129 + 75*128) * 4)   /* 71424 B */

__global__ __launch_bounds__(256) void kpool(const float* __restrict__ sup,
                                             const float* __restrict__ qry) {
    extern __shared__ float ps_sm[];
    int t = threadIdx.x;

    if (blockIdx.x < WAY*10) {
        float* xs  = ps_sm;              // [64][129]
        float* asb = ps_sm + 64*129;     // [75][128]
        int w = blockIdx.x / 10, ct = blockIdx.x % 10;
        int c0 = ct*64;
        int c = t & 63, qb = t >> 6;
        const float* X = sup + (size_t)w*CIN*NTOK + (size_t)c0*NTOK;

        float acc[19];
        #pragma unroll
        for (int j = 0; j < 19; j++) acc[j] = 0.f;

        for (int i0 = 0; i0 < NTOK; i0 += 128) {
            __syncthreads();
            for (int idx = t; idx < 64*32; idx += 256) {
                int r = idx >> 5, i4 = (idx & 31) << 2;
                float4 v = *(const float4*)(X + (size_t)r*NTOK + i0 + i4);
                xs[r*129 + i4+0] = v.x; xs[r*129 + i4+1] = v.y;
                xs[r*129 + i4+2] = v.z; xs[r*129 + i4+3] = v.w;
            }
            for (int idx = t; idx < 75*32; idx += 256) {
                int r = idx / 32, i4 = (idx & 31) << 2;
                *(float4*)&asb[r*128 + i4] =
                    *(const float4*)(g_as + (size_t)(r*WAY + w)*NTOK + i0 + i4);
            }
            __syncthreads();
            for (int i = 0; i < 128; i += 4) {
                float x0 = xs[c*129 + i],   x1 = xs[c*129 + i+1];
                float x2 = xs[c*129 + i+2], x3 = xs[c*129 + i+3];
                #pragma unroll
                for (int j = 0; j < 19; j++) {
                    int q = qb + 4*j;
                    if (q < NQ) {
                        float4 a = *(float4*)&asb[q*128 + i];
                        acc[j] = fmaf(a.x, x0, fmaf(a.y, x1, fmaf(a.z, x2, fmaf(a.w, x3, acc[j]))));
                    }
                }
            }
        }
        #pragma unroll
        for (int j = 0; j < 19; j++) {
            int q = qb + 4*j;
            if (q < NQ) g_ps[(size_t)(q*WAY + w)*CIN + c0 + c] = acc[j];
        }
    } else {
        float* xs  = ps_sm;              // [64][129]
        float* aqb = ps_sm + 64*129;     // [5][128]
        float* red = aqb + 5*128;        // [5*64][4]
        int bidq = blockIdx.x - WAY*10;
        int q = bidq / 10, ct = bidq % 10;
        int c0 = ct*64;
        int c = t & 63, g = t >> 6;
        const float* X = qry + (size_t)q*CIN*NTOK + (size_t)c0*NTOK;

        float acc[5] = {0.f, 0.f, 0.f, 0.f, 0.f};

        for (int i0 = 0; i0 < NTOK; i0 += 128) {
            __syncthreads();
            for (int idx = t; idx < 64*32; idx += 256) {
                int r = idx >> 5, i4 = (idx & 31) << 2;
                float4 v = *(const float4*)(X + (size_t)r*NTOK + i0 + i4);
                xs[r*129 + i4+0] = v.x; xs[r*129 + i4+1] = v.y;
                xs[r*129 + i4+2] = v.z; xs[r*129 + i4+3] = v.w;
            }
            for (int idx = t; idx < 5*32; idx += 256) {
                int r = idx / 32, i4 = (idx & 31) << 2;
                *(float4*)&aqb[r*128 + i4] =
                    *(const float4*)(g_aq + (size_t)(q*WAY + r)*NTOK + i0 + i4);
            }
            __syncthreads();
            for (int i = g*32; i < g*32 + 32; i += 4) {
                float x0 = xs[c*129 + i],   x1 = xs[c*129 + i+1];
                float x2 = xs[c*129 + i+2], x3 = xs[c*129 + i+3];
                #pragma unroll
                for (int wv = 0; wv < 5; wv++) {
                    float4 a = *(float4*)&aqb[wv*128 + i];
                    acc[wv] = fmaf(a.x, x0, fmaf(a.y, x1, fmaf(a.z, x2, fmaf(a.w, x3, acc[wv]))));
                }
            }
        }
        #pragma unroll
        for (int wv = 0; wv < 5; wv++) red[(wv*64 + c)*4 + g] = acc[wv];
        __syncthreads();
        for (int idx = t; idx < 5*64; idx += 256) {
            int wv = idx >> 6, cc = idx & 63;
            float s = red[idx*4] + red[idx*4+1] + red[idx*4+2] + red[idx*4+3];
            g_pq[(size_t)(q*WAY + wv)*CIN + c0 + cc] = s;
        }
    }
}

/* ------------- Kcos: mean corrections + cosine sim ------------- */
__global__ __launch_bounds__(128) void kcos(float* __restrict__ out) {
    __shared__ float rbuf[4*5];
    int pair = blockIdx.x, q = pair / WAY, w = pair % WAY;
    int t = threadIdx.x, lane = t & 31, wp = t >> 5;

    float cS = 0.f, cQ = 0.f;
    for (int i = t; i < NTOK; i += 128) {
        cS = fmaf(g_as[pair*NTOK + i], g_mS[w*NTOK + i], cS);
        cQ = fmaf(g_aq[pair*NTOK + i], g_mQ[q*NTOK + i], cQ);
    }
    cS = warp_sum(cS); cQ = warp_sum(cQ);
    if (lane == 0) { rbuf[wp*5+0] = cS; rbuf[wp*5+1] = cQ; }
    __syncthreads();
    cS = rbuf[0] + rbuf[5] + rbuf[10] + rbuf[15];
    cQ = rbuf[1] + rbuf[6] + rbuf[11] + rbuf[16];
    __syncthreads();

    float dp = 0.f, ns = 0.f, nq2 = 0.f;
    for (int c = t; c < CIN; c += 128) {
        float a = g_ps[(size_t)pair*CIN + c] - cS;
        float b = g_pq[(size_t)pair*CIN + c] - cQ;
        dp = fmaf(a, b, dp); ns = fmaf(a, a, ns); nq2 = fmaf(b, b, nq2);
    }
    dp = warp_sum(dp); ns = warp_sum(ns); nq2 = warp_sum(nq2);
    if (lane == 0) { rbuf[wp*5+0] = dp; rbuf[wp*5+1] = ns; rbuf[wp*5+2] = nq2; }
    __syncthreads();
    if (t == 0) {
        dp  = rbuf[0] + rbuf[5] + rbuf[10] + rbuf[15];
        ns  = rbuf[1] + rbuf[6] + rbuf[11] + rbuf[16];
        nq2 = rbuf[2] + rbuf[7] + rbuf[12] + rbuf[17];
        float psn = fmaxf(sqrtf(ns)  * (1.f/512.f), L2_EPS);
        float pqn = fmaxf(sqrtf(nq2) * (1.f/512.f), L2_EPS);
        out[pair] = (dp * (1.f/(512.f*512.f))) / (psn * pqn) * 5.f;
    }
}

/* ------------- launcher ------------- */
extern "C" void kernel_launch(void* const* d_in, const int* in_sizes, int n_in,
                              void* d_out, int out_size) {
    const float* sup   = (const float*)d_in[0];
    const float* qry   = (const float*)d_in[1];
    const float* W     = (const float*)d_in[2];
    const float* gamma = (const float*)d_in[3];
    const float* beta  = (const float*)d_in[4];
    const float* mean  = (const float*)d_in[5];
    const float* var   = (const float*)d_in[6];
    float* out = (float*)d_out;

    cudaFuncSetAttribute(kpass, cudaFuncAttributeMaxDynamicSharedMemorySize, KP_SMEM_BYTES);
    cudaFuncSetAttribute(kproj, cudaFuncAttributeMaxDynamicSharedMemorySize, PJ_SMEM);
    cudaFuncSetAttribute(kpool, cudaFuncAttributeMaxDynamicSharedMemorySize, PS_SMEM);

    kproj<<<(WAY+NQ)*4, 256, PJ_SMEM>>>(sup, qry, W, gamma, beta, mean, var);
    kgram<<<WAY+NQ, 256>>>();
    kpass<<<2*PAIRS, 256, KP_SMEM_BYTES>>>();
    kpool<<<WAY*10 + NQ*10, 256, PS_SMEM>>>(sup, qry);
    kcos<<<PAIRS, 128>>>(out);
}